// round 1
// baseline (speedup 1.0000x reference)
#include <cuda_runtime.h>
#include <math.h>

#define SIZE   512
#define NB     16
#define NSEG   10
#define TILE   32

// Per-(batch,segment): vy,vx,dy,dx,invd2, ylo,yhi,xlo,xhi  (AABB pre-expanded by thick)
__device__ float g_segs[NB * NSEG * 9];
// Per-batch: thick, 1/thick
__device__ float g_thick[NB * 2];

__device__ __forceinline__ void bez_point(const float* cy, const float* cx, int p,
                                          float& py, float& px) {
    const int start0 = 10, start1 = 6, start2 = 3, start3 = 0;
    if (p < 10) {
        float sy = 0.f, sx = 0.f;
        int starts[4] = {start0, start1, start2, start3};
        #pragma unroll
        for (int k = 0; k < 4; k++) {
            float n = (float)(starts[k] + p) - 9.5f;
            float h = n * 0.5f;
            float w = 0.75f * expf(-0.5f * h * h);
            sy += cy[k] * w;
            sx += cx[k] * w;
        }
        py = sy * 512.0f;
        px = sx * 512.0f;
    } else {
        py = cy[3] * 512.0f;
        px = cx[3] * 512.0f;
    }
}

__global__ void bez_precompute(const float* __restrict__ traj,
                               const float* __restrict__ thin) {
    int t = threadIdx.x;
    if (t >= NB * NSEG) return;
    int b = t / NSEG;
    int s = t % NSEG;

    float cy[4], cx[4];
    #pragma unroll
    for (int k = 0; k < 4; k++) {
        cy[k] = traj[b * 8 + k];       // c = 0 (y)
        cx[k] = traj[b * 8 + 4 + k];   // c = 1 (x)
    }

    float vy, vx, wy, wx;
    bez_point(cy, cx, s,     vy, vx);
    bez_point(cy, cx, s + 1, wy, wx);

    float dy = wy - vy, dx = wx - vx;
    float d2 = dy * dy + dx * dx;
    float invd2 = 1.0f / (d2 + 1e-5f);

    float th = 0.f;
    #pragma unroll
    for (int k = 0; k < 4; k++) th += thin[b * 4 + k] * 2.0f + 0.5f;
    float thick = 2.0f * th;

    float* o = g_segs + t * 9;
    o[0] = vy; o[1] = vx; o[2] = dy; o[3] = dx; o[4] = invd2;
    o[5] = fminf(vy, wy) - thick;
    o[6] = fmaxf(vy, wy) + thick;
    o[7] = fminf(vx, wx) - thick;
    o[8] = fmaxf(vx, wx) + thick;

    if (s == 0) {
        g_thick[b * 2]     = thick;
        g_thick[b * 2 + 1] = 1.0f / thick;
    }
}

// Block: (32,4) threads, tile 32x32 pixels, 8 rows per thread (stride 4).
__global__ __launch_bounds__(128) void bez_render(float* __restrict__ out) {
    __shared__ float ssg[NSEG * 9];
    __shared__ float sth[2];
    __shared__ int   smask;

    int b   = blockIdx.z;
    int tx0 = blockIdx.x * TILE;
    int ty0 = blockIdx.y * TILE;
    int tid = threadIdx.y * 32 + threadIdx.x;

    if (tid < NSEG * 9) ssg[tid] = g_segs[b * NSEG * 9 + tid];
    if (tid == 96) sth[0] = g_thick[b * 2];
    if (tid == 97) sth[1] = g_thick[b * 2 + 1];
    if (tid == 0)  smask = 0;
    __syncthreads();

    if (tid < NSEG) {
        const float* sg = ssg + tid * 9;
        float ty1 = (float)(ty0 + TILE - 1);
        float tx1 = (float)(tx0 + TILE - 1);
        bool act = (sg[6] >= (float)ty0) && (sg[5] <= ty1) &&
                   (sg[8] >= (float)tx0) && (sg[7] <= tx1);
        if (act) atomicOr(&smask, 1 << tid);
    }
    __syncthreads();

    int mask = smask;
    float* outb = out + (size_t)b * SIZE * SIZE;

    if (mask == 0) {
        // Entire tile is zero: vectorized fill. 32x32 tile = 256 float4.
        float4 z = make_float4(0.f, 0.f, 0.f, 0.f);
        #pragma unroll
        for (int k = 0; k < 2; k++) {
            int idx = tid + k * 128;
            int row = idx >> 3;
            int c4  = idx & 7;
            *(float4*)(outb + (size_t)(ty0 + row) * SIZE + tx0 + c4 * 4) = z;
        }
        return;
    }

    float x     = (float)(tx0 + threadIdx.x);
    float ybase = (float)(ty0 + threadIdx.y);

    float dmin[8];
    #pragma unroll
    for (int j = 0; j < 8; j++) dmin[j] = 3.0e38f;

    while (mask) {
        int s = __ffs(mask) - 1;
        mask &= mask - 1;
        const float* sg = ssg + s * 9;
        float vy = sg[0], vx = sg[1], dy = sg[2], dx = sg[3], invd2 = sg[4];

        float pvx  = x - vx;        // invariant over rows
        float pxdx = pvx * dx;
        float pvy0 = ybase - vy;

        #pragma unroll
        for (int j = 0; j < 8; j++) {
            float pvy = pvy0 + (float)(4 * j);
            float dot = fmaf(pvy, dy, pxdx);
            float t   = __saturatef(dot * invd2);
            float ry  = fmaf(-t, dy, pvy);
            float rx  = fmaf(-t, dx, pvx);
            float dd  = fmaf(ry, ry, rx * rx);
            dmin[j]   = fminf(dmin[j], dd);
        }
    }

    float thick = sth[0], invth = sth[1];
    #pragma unroll
    for (int j = 0; j < 8; j++) {
        float dist = sqrtf(dmin[j]);
        float dark = __saturatef((thick - dist) * invth);
        outb[(size_t)(ty0 + threadIdx.y + 4 * j) * SIZE + tx0 + threadIdx.x] = dark;
    }
}

extern "C" void kernel_launch(void* const* d_in, const int* in_sizes, int n_in,
                              void* d_out, int out_size) {
    const float* traj = (const float*)d_in[0];   // (16,2,4)
    const float* thin = (const float*)d_in[1];   // (16,1,4)
    float* out = (float*)d_out;                  // (16,512,512) f32

    bez_precompute<<<1, NB * NSEG>>>(traj, thin);

    dim3 grid(SIZE / TILE, SIZE / TILE, NB);
    dim3 block(32, 4);
    bez_render<<<grid, block>>>(out);
}

// round 2
// speedup vs baseline: 1.0373x; 1.0373x over previous
#include <cuda_runtime.h>
#include <math.h>

#define SIZE 512
#define NB   16
#define NSEG 10
#define TX   32
#define TY   64

// Single fused kernel. Block (32,8) = 256 threads renders a 32x64 tile.
// Warp 0 recomputes the batch's segment params from the 12 input floats
// (cheap: weights are exp() of compile-time-known arguments), builds the
// per-tile active-segment mask via AABB test + ballot. Tiles with no
// active segment degenerate to vectorized zero fill.
__global__ __launch_bounds__(256) void bez_render(
    const float* __restrict__ traj,   // (16,2,4)
    const float* __restrict__ thin,   // (16,1,4)
    float* __restrict__ out)          // (16,512,512)
{
    __shared__ float    spts[11][2];      // [p][coord: 0=y,1=x], scaled by 512
    __shared__ float    ssg[NSEG][5];     // vy,vx,dy,dx,invd2
    __shared__ float    sth[2];           // thick, 1/thick
    __shared__ unsigned smask;

    int b   = blockIdx.z;
    int tx0 = blockIdx.x * TX;
    int ty0 = blockIdx.y * TY;
    int tid = threadIdx.y * 32 + threadIdx.x;

    if (tid < 32) {
        // --- Phase A: 22 threads compute the 11 stroke points (one coord each) ---
        if (tid < 22) {
            int p = tid >> 1;
            int c = tid & 1;
            const float* cc = traj + b * 8 + c * 4;   // traj[b, c, :]
            float v;
            if (p < 10) {
                const int starts[4] = {10, 6, 3, 0};
                float s = 0.f;
                #pragma unroll
                for (int k = 0; k < 4; k++) {
                    float n = (float)(starts[k] + p) - 9.5f;
                    float h = n * 0.5f;
                    float w = 0.75f * expf(-0.5f * h * h);
                    s = fmaf(cc[k], w, s);
                }
                v = s * 512.0f;
            } else {
                v = cc[3] * 512.0f;   // last = traj[:, :, 3]
            }
            spts[p][c] = v;
        }
        if (tid == 22) {
            float th = 0.f;
            #pragma unroll
            for (int k = 0; k < 4; k++) th += thin[b * 4 + k] * 2.0f + 0.5f;
            float thick = 2.0f * th;
            sth[0] = thick;
            sth[1] = 1.0f / thick;
        }
        __syncwarp();

        // --- Phase B: 10 threads build segment params + tile AABB test ---
        bool act = false;
        if (tid < NSEG) {
            float vy = spts[tid][0],     vx = spts[tid][1];
            float wy = spts[tid + 1][0], wx = spts[tid + 1][1];
            float dy = wy - vy, dx = wx - vx;
            float invd2 = 1.0f / (dy * dy + dx * dx + 1e-5f);
            ssg[tid][0] = vy; ssg[tid][1] = vx;
            ssg[tid][2] = dy; ssg[tid][3] = dx; ssg[tid][4] = invd2;

            float thick = sth[0];
            float ylo = fminf(vy, wy) - thick, yhi = fmaxf(vy, wy) + thick;
            float xlo = fminf(vx, wx) - thick, xhi = fmaxf(vx, wx) + thick;
            act = (yhi >= (float)ty0) && (ylo <= (float)(ty0 + TY - 1)) &&
                  (xhi >= (float)tx0) && (xlo <= (float)(tx0 + TX - 1));
        }
        unsigned m = __ballot_sync(0xffffffff, act);
        if (tid == 0) smask = m;
    }
    __syncthreads();

    unsigned mask = smask;
    float* outb = out + (size_t)b * SIZE * SIZE;

    if (mask == 0) {
        // Whole tile is zero: 64 rows x 32 cols = 512 float4, 2 per thread.
        float4 z = make_float4(0.f, 0.f, 0.f, 0.f);
        #pragma unroll
        for (int k = 0; k < 2; k++) {
            int idx = tid + k * 256;
            int row = idx >> 3;
            int c4  = idx & 7;
            *(float4*)(outb + (size_t)(ty0 + row) * SIZE + tx0 + c4 * 4) = z;
        }
        return;
    }

    float x     = (float)(tx0 + threadIdx.x);
    float ybase = (float)(ty0 + threadIdx.y);

    float dmin[8];
    #pragma unroll
    for (int j = 0; j < 8; j++) dmin[j] = 3.0e38f;

    while (mask) {
        int s = __ffs(mask) - 1;
        mask &= mask - 1;
        const float* sg = ssg[s];
        float vy = sg[0], vx = sg[1], dy = sg[2], dx = sg[3], invd2 = sg[4];

        float pvx  = x - vx;          // row-invariant
        float pxdx = pvx * dx;
        float pvy0 = ybase - vy;

        #pragma unroll
        for (int j = 0; j < 8; j++) {
            float pvy = pvy0 + (float)(8 * j);
            float dot = fmaf(pvy, dy, pxdx);
            float t   = __saturatef(dot * invd2);
            float ry  = fmaf(-t, dy, pvy);
            float rx  = fmaf(-t, dx, pvx);
            float dd  = fmaf(ry, ry, rx * rx);
            dmin[j]   = fminf(dmin[j], dd);
        }
    }

    float thick = sth[0], invth = sth[1];
    #pragma unroll
    for (int j = 0; j < 8; j++) {
        float dist = sqrtf(dmin[j]);
        float dark = __saturatef((thick - dist) * invth);
        outb[(size_t)(ty0 + threadIdx.y + 8 * j) * SIZE + tx0 + threadIdx.x] = dark;
    }
}

extern "C" void kernel_launch(void* const* d_in, const int* in_sizes, int n_in,
                              void* d_out, int out_size) {
    const float* traj = (const float*)d_in[0];
    const float* thin = (const float*)d_in[1];
    float* out = (float*)d_out;

    dim3 grid(SIZE / TX, SIZE / TY, NB);
    dim3 block(32, 8);
    bez_render<<<grid, block>>>(traj, thin, out);
}

// round 3
// speedup vs baseline: 1.0570x; 1.0190x over previous
#include <cuda_runtime.h>
#include <math.h>

#define SIZE 512
#define NB   16
#define NSEG 10

// One block = one batch x one 64x64 region = 2x2 tiles of 32x32.
// Grid: (64, 1, 16) -> 1024 blocks (single wave on 148 SMs @ 8 blocks/SM).
// Warp 0 computes the batch's 11 stroke points (exp of compile-time args),
// segment params, and 4 per-tile active-segment masks. Zero tiles -> float4
// fill; active tiles -> min-squared-distance loop, one sqrt per pixel.
__global__ __launch_bounds__(256) void bez_render(
    const float* __restrict__ traj,   // (16,2,4)
    const float* __restrict__ thin,   // (16,1,4)
    float* __restrict__ out)          // (16,512,512)
{
    __shared__ float    spts[11][2];     // [p][0=y,1=x], scaled by 512
    __shared__ float    ssg[NSEG][5];    // vy,vx,dy,dx,invd2
    __shared__ float    sth[2];          // thick, 1/thick
    __shared__ unsigned smask[4];

    int b   = blockIdx.z;
    int g   = blockIdx.x;                // 0..63
    int rx0 = (g & 7) << 6;              // region origin
    int ry0 = (g >> 3) << 6;
    int tid = threadIdx.y * 32 + threadIdx.x;

    if (tid < 32) {
        // Phase A: 22 threads compute the 11 stroke points (one coord each).
        if (tid < 22) {
            int p = tid >> 1;
            int c = tid & 1;
            const float* cc = traj + b * 8 + c * 4;
            float v;
            if (p < 10) {
                const int starts[4] = {10, 6, 3, 0};
                float s = 0.f;
                #pragma unroll
                for (int k = 0; k < 4; k++) {
                    float n = (float)(starts[k] + p) - 9.5f;
                    float h = n * 0.5f;
                    float w = 0.75f * expf(-0.5f * h * h);
                    s = fmaf(cc[k], w, s);
                }
                v = s * 512.0f;
            } else {
                v = cc[3] * 512.0f;
            }
            spts[p][c] = v;
        }
        if (tid == 22) {
            float th = 0.f;
            #pragma unroll
            for (int k = 0; k < 4; k++) th += thin[b * 4 + k] * 2.0f + 0.5f;
            float thick = 2.0f * th;
            sth[0] = thick;
            sth[1] = 1.0f / thick;
        }
        __syncwarp();

        // Phase B: 10 threads build segment params + thick-expanded AABBs.
        float ylo = 0.f, yhi = -1.f, xlo = 0.f, xhi = -1.f;
        if (tid < NSEG) {
            float vy = spts[tid][0],     vx = spts[tid][1];
            float wy = spts[tid + 1][0], wx = spts[tid + 1][1];
            float dy = wy - vy, dx = wx - vx;
            ssg[tid][0] = vy; ssg[tid][1] = vx;
            ssg[tid][2] = dy; ssg[tid][3] = dx;
            ssg[tid][4] = 1.0f / (dy * dy + dx * dx + 1e-5f);
            float thick = sth[0];
            ylo = fminf(vy, wy) - thick; yhi = fmaxf(vy, wy) + thick;
            xlo = fminf(vx, wx) - thick; xhi = fmaxf(vx, wx) + thick;
        }
        // 4 per-tile masks via ballot (whole warp 0 participates).
        #pragma unroll
        for (int t = 0; t < 4; t++) {
            float tx0 = (float)(rx0 + ((t & 1) << 5));
            float ty0 = (float)(ry0 + ((t >> 1) << 5));
            bool act = (tid < NSEG) &&
                       (yhi >= ty0) && (ylo <= ty0 + 31.f) &&
                       (xhi >= tx0) && (xlo <= tx0 + 31.f);
            unsigned m = __ballot_sync(0xffffffff, act);
            if (tid == 0) smask[t] = m;
        }
    }
    __syncthreads();

    float* outb = out + (size_t)b * SIZE * SIZE;
    float thick = sth[0], invth = sth[1];

    #pragma unroll
    for (int t = 0; t < 4; t++) {
        int tx0 = rx0 + ((t & 1) << 5);
        int ty0 = ry0 + ((t >> 1) << 5);
        unsigned mask = smask[t];

        if (mask == 0) {
            // 32x32 zeros = 256 float4: exactly one per thread.
            int row = tid >> 3;
            int c4  = tid & 7;
            *(float4*)(outb + (size_t)(ty0 + row) * SIZE + tx0 + c4 * 4) =
                make_float4(0.f, 0.f, 0.f, 0.f);
            continue;
        }

        float x     = (float)(tx0 + threadIdx.x);
        float ybase = (float)(ty0 + threadIdx.y);

        float dmin[4];
        #pragma unroll
        for (int j = 0; j < 4; j++) dmin[j] = 3.0e38f;

        unsigned m = mask;
        while (m) {
            int s = __ffs(m) - 1;
            m &= m - 1;
            const float* sg = ssg[s];
            float vy = sg[0], vx = sg[1], dy = sg[2], dx = sg[3], invd2 = sg[4];

            float pvx  = x - vx;           // row-invariant
            float pxdx = pvx * dx;
            float pvy0 = ybase - vy;

            #pragma unroll
            for (int j = 0; j < 4; j++) {
                float pvy = pvy0 + (float)(8 * j);
                float dot = fmaf(pvy, dy, pxdx);
                float tt  = __saturatef(dot * invd2);
                float ry  = fmaf(-tt, dy, pvy);
                float rx  = fmaf(-tt, dx, pvx);
                float dd  = fmaf(ry, ry, rx * rx);
                dmin[j]   = fminf(dmin[j], dd);
            }
        }

        #pragma unroll
        for (int j = 0; j < 4; j++) {
            float dist = sqrtf(dmin[j]);
            float dark = __saturatef((thick - dist) * invth);
            outb[(size_t)(ty0 + threadIdx.y + 8 * j) * SIZE + tx0 + threadIdx.x] = dark;
        }
    }
}

extern "C" void kernel_launch(void* const* d_in, const int* in_sizes, int n_in,
                              void* d_out, int out_size) {
    const float* traj = (const float*)d_in[0];
    const float* thin = (const float*)d_in[1];
    float* out = (float*)d_out;

    dim3 grid(64, 1, NB);
    dim3 block(32, 8);
    bez_render<<<grid, block>>>(traj, thin, out);
}

// round 4
// speedup vs baseline: 1.2014x; 1.1367x over previous
#include <cuda_runtime.h>
#include <math.h>

#define SIZE   512
#define NB     16
#define NSEG   10
#define NBLK   592           // 4 blocks/SM on 148 SMs
#define NTHR   256
#define WPB    (NTHR / 32)
#define NWARP  (NBLK * WPB)
// Strip = 32 wide x 8 tall. Per batch: 16 x-strips * 64 y-strips = 1024.
#define NSTRIP (NB * 1024)

__global__ __launch_bounds__(NTHR) void bez_render(
    const float* __restrict__ traj,   // (16,2,4)
    const float* __restrict__ thin,   // (16,1,4)
    float* __restrict__ out)          // (16,512,512)
{
    __shared__ float  sW[40];          // bezier weights [k][p]
    __shared__ float  straj[NB * 8];
    __shared__ float  sthin[NB * 4];
    __shared__ float4 sp4[NB][NSEG];   // vy,vx,dy,dx
    __shared__ float  sinv[NB][NSEG];  // 1/(d2+1e-5)
    __shared__ float4 sab[NB][NSEG];   // ylo,yhi,xlo,xhi (thick-expanded)
    __shared__ float2 sthk[NB];        // thick, 1/thick

    int tid = threadIdx.x;

    // ---- Setup phase 1: stage inputs + weight table ----
    if (tid < 128) {
        straj[tid] = traj[tid];
    } else if (tid < 192) {
        sthin[tid - 128] = thin[tid - 128];
    } else if (tid < 232) {
        int i = tid - 192;
        int k = i / 10, p = i % 10;
        const int starts[4] = {10, 6, 3, 0};
        float n = (float)(starts[k] + p) - 9.5f;
        sW[i] = 0.75f * expf(-0.125f * n * n);
    }
    __syncthreads();

    // ---- Setup phase 2: 160 threads build 160 segments ----
    if (tid < NB * NSEG) {
        int b = tid / NSEG;
        int s = tid % NSEG;
        const float* cy = straj + b * 8;       // y control points
        const float* cx = straj + b * 8 + 4;   // x control points

        float pt[2][2];   // [end 0/1][coord y/x]
        #pragma unroll
        for (int e = 0; e < 2; e++) {
            int p = s + e;
            if (p < 10) {
                float sy = 0.f, sx = 0.f;
                #pragma unroll
                for (int k = 0; k < 4; k++) {
                    float w = sW[k * 10 + p];
                    sy = fmaf(cy[k], w, sy);
                    sx = fmaf(cx[k], w, sx);
                }
                pt[e][0] = sy * 512.0f;
                pt[e][1] = sx * 512.0f;
            } else {
                pt[e][0] = cy[3] * 512.0f;
                pt[e][1] = cx[3] * 512.0f;
            }
        }
        float vy = pt[0][0], vx = pt[0][1];
        float wy = pt[1][0], wx = pt[1][1];
        float dy = wy - vy, dx = wx - vx;

        float th = 0.f;
        #pragma unroll
        for (int k = 0; k < 4; k++) th += sthin[b * 4 + k] * 2.0f + 0.5f;
        float thick = 2.0f * th;

        sp4[b][s]  = make_float4(vy, vx, dy, dx);
        sinv[b][s] = 1.0f / (dy * dy + dx * dx + 1e-5f);
        sab[b][s]  = make_float4(fminf(vy, wy) - thick, fmaxf(vy, wy) + thick,
                                 fminf(vx, wx) - thick, fmaxf(vx, wx) + thick);
        if (s == 0) sthk[b] = make_float2(thick, 1.0f / thick);
    }
    __syncthreads();

    // ---- Main loop: warps grid-stride over 32x8 strips. No barriers. ----
    int wid  = tid >> 5;
    int lane = tid & 31;
    int gw   = blockIdx.x * WPB + wid;

    for (int sid = gw; sid < NSTRIP; sid += NWARP) {
        int b  = sid >> 10;
        int r  = sid & 1023;
        int y0 = (r >> 4) << 3;   // 0..504 step 8
        int x0 = (r & 15) << 5;   // 0..480 step 32
        float y0f = (float)y0;
        float x0f = (float)x0;

        bool act = false;
        if (lane < NSEG) {
            float4 ab = sab[b][lane];
            act = (ab.y >= y0f) && (ab.x <= y0f + 7.f) &&
                  (ab.w >= x0f) && (ab.z <= x0f + 31.f);
        }
        unsigned m = __ballot_sync(0xffffffffu, act);

        float* op = out + ((size_t)b << 18) + (size_t)y0 * SIZE + x0;

        if (m == 0) {
            // 8 rows x 32 cols of zeros = 64 float4, 2 per lane.
            float4 z = make_float4(0.f, 0.f, 0.f, 0.f);
            int r0 = lane >> 3, c0 = lane & 7;
            *(float4*)(op + r0 * SIZE + c0 * 4)       = z;
            *(float4*)(op + (r0 + 4) * SIZE + c0 * 4) = z;
            continue;
        }

        float x = x0f + (float)lane;
        float dmin[8];
        #pragma unroll
        for (int j = 0; j < 8; j++) dmin[j] = 3.0e38f;

        while (m) {
            int s = __ffs(m) - 1;
            m &= m - 1;
            float4 p4 = sp4[b][s];
            float  iv = sinv[b][s];
            float vy = p4.x, vx = p4.y, dy = p4.z, dx = p4.w;

            float pvx  = x - vx;        // row-invariant for this lane
            float pxdx = pvx * dx;
            float pvy0 = y0f - vy;

            #pragma unroll
            for (int j = 0; j < 8; j++) {
                float pvy = pvy0 + (float)j;
                float dot = fmaf(pvy, dy, pxdx);
                float t   = __saturatef(dot * iv);
                float ry  = fmaf(-t, dy, pvy);
                float rx  = fmaf(-t, dx, pvx);
                float dd  = fmaf(ry, ry, rx * rx);
                dmin[j]   = fminf(dmin[j], dd);
            }
        }

        float2 tk = sthk[b];
        #pragma unroll
        for (int j = 0; j < 8; j++) {
            float dist = sqrtf(dmin[j]);
            float dark = __saturatef((tk.x - dist) * tk.y);
            op[j * SIZE + lane] = dark;
        }
    }
}

extern "C" void kernel_launch(void* const* d_in, const int* in_sizes, int n_in,
                              void* d_out, int out_size) {
    const float* traj = (const float*)d_in[0];
    const float* thin = (const float*)d_in[1];
    float* out = (float*)d_out;

    bez_render<<<NBLK, NTHR>>>(traj, thin, out);
}